// round 5
// baseline (speedup 1.0000x reference)
#include <cuda_runtime.h>
#include <cuda_bf16.h>
#include <cstdint>

// Problem constants
#define NROWS 32768
#define DIMK  512
#define NCB   16
#define CS    256

// Encoder tiling
#define TM    128
#define TN    256
#define KC    32
#define NCHUNK (DIMK / KC)   // 16
#define TPB   512

#define RECHECK_CAP 65536
#define RECHECK_BLOCKS 8192
#define GAP_TAU 2e-3f

__device__ int g_idx[NROWS * NCB];
__device__ int g_cnt;
__device__ int g_list[RECHECK_CAP];

// ---------------- smem layout (dynamic) ----------------
#define SM_BIAS 0          // 256 f32 = 1024B
#define SM_V1   1024       // 128*4 f32 = 2048B
#define SM_V2   3072       // 2048B
#define SM_I1   5120       // 2048B (int)
#define SM_BUF  7168       // 2 x 61440
#define ASTR    80         // bytes per k-row (32 bf16 = 64B + 16B pad)
#define OFF_AH  0
#define OFF_AL  10240      // 128*80
#define OFF_BH  20480
#define OFF_BL  40960      // +256*80
#define BUFSZ   61440
#define SMEM_TOTAL (SM_BUF + 2 * BUFSZ)   // 130048 B

__device__ __forceinline__ uint32_t smem_u32(const void* p) {
    uint32_t a;
    asm("{ .reg .u64 t; cvta.to.shared.u64 t, %1; cvt.u32.u64 %0, t; }"
        : "=r"(a) : "l"(p));
    return a;
}
__device__ __forceinline__ void ldm4(uint32_t r[4], uint32_t addr) {
    asm volatile("ldmatrix.sync.aligned.m8n8.x4.shared.b16 {%0,%1,%2,%3}, [%4];"
        : "=r"(r[0]), "=r"(r[1]), "=r"(r[2]), "=r"(r[3]) : "r"(addr));
}
__device__ __forceinline__ void mma_bf16(float d[4], const uint32_t a[4],
                                         uint32_t b0, uint32_t b1) {
    asm volatile("mma.sync.aligned.m16n8k16.row.col.f32.bf16.bf16.f32 "
        "{%0,%1,%2,%3},{%4,%5,%6,%7},{%8,%9},{%0,%1,%2,%3};"
        : "+f"(d[0]), "+f"(d[1]), "+f"(d[2]), "+f"(d[3])
        : "r"(a[0]), "r"(a[1]), "r"(a[2]), "r"(a[3]), "r"(b0), "r"(b1));
}

struct BF2 { uint32_t h, l; };
__device__ __forceinline__ BF2 split2(float a, float b) {
    __nv_bfloat16 ha = __float2bfloat16_rn(a);
    __nv_bfloat16 hb = __float2bfloat16_rn(b);
    float la = a - __bfloat162float(ha);
    float lb = b - __bfloat162float(hb);
    __nv_bfloat162 hp, lp;
    hp.x = ha; hp.y = hb;
    lp.x = __float2bfloat16_rn(la); lp.y = __float2bfloat16_rn(lb);
    BF2 r;
    r.h = *reinterpret_cast<uint32_t*>(&hp);
    r.l = *reinterpret_cast<uint32_t*>(&lp);
    return r;
}

// ---------------------------------------------------------------------------
// Kernel 1: bf16 3-pass split GEMM (mma.sync) + argmax + near-tie list.
// grid = (NROWS/TM, NCB), block = 512 (16 warps, 4m x 4n, warp tile 32x64).
// ---------------------------------------------------------------------------
__global__ __launch_bounds__(TPB, 1)
void enc_mma_kernel(const float* __restrict__ x,
                    const float* __restrict__ W,
                    const float* __restrict__ bias,
                    int* __restrict__ gidx)
{
    extern __shared__ char smem[];
    const uint32_t sb = smem_u32(smem);
    const int tid  = threadIdx.x;
    const int lane = tid & 31;
    const int wid  = tid >> 5;
    const int wm   = wid >> 2;    // 0..3
    const int wn   = wid & 3;     // 0..3
    const int cb   = blockIdx.y;
    const int row0 = blockIdx.x * TM;

    if (tid < CS)
        *reinterpret_cast<float*>(smem + SM_BIAS + tid * 4) = bias[cb * CS + tid];

    const float* xg = x + (size_t)row0 * DIMK;
    const float* Wg = W + (size_t)cb * CS * DIMK;

    float acc[2][8][4];
    #pragma unroll
    for (int i = 0; i < 2; ++i)
        #pragma unroll
        for (int j = 0; j < 8; ++j)
            #pragma unroll
            for (int k = 0; k < 4; ++k) acc[i][j][k] = 0.f;

    // precomputed per-lane ldmatrix address offsets (bytes, within a buffer)
    const uint32_t a_off = (uint32_t)((wm * 32 + (lane & 15)) * ASTR + ((lane >> 4) * 16));
    const uint32_t b_off = (uint32_t)((wn * 64 + (lane & 7) + ((lane & 16) >> 1)) * ASTR
                                      + (((lane >> 3) & 1) * 16));

    // ---- staging ----
    const int ar = tid >> 2, asg = tid & 3;        // A: row, 8-float segment
    const int bc = tid >> 1, bsg = tid & 1;        // B: col, 16-float segment

    #define STAGE(k0, bufp) do {                                                   \
        { /* A tile: 128x32 fp32 */                                                \
            const float4* s = reinterpret_cast<const float4*>(                     \
                xg + (size_t)ar * DIMK + (k0) + asg * 8);                           \
            float4 f0 = s[0], f1 = s[1];                                           \
            BF2 p0 = split2(f0.x, f0.y), p1 = split2(f0.z, f0.w);                   \
            BF2 p2 = split2(f1.x, f1.y), p3 = split2(f1.z, f1.w);                   \
            *reinterpret_cast<uint4*>((bufp) + OFF_AH + ar * ASTR + asg * 16) =     \
                make_uint4(p0.h, p1.h, p2.h, p3.h);                                 \
            *reinterpret_cast<uint4*>((bufp) + OFF_AL + ar * ASTR + asg * 16) =     \
                make_uint4(p0.l, p1.l, p2.l, p3.l);                                 \
        }                                                                          \
        { /* B tile: 256x32 fp32 */                                                \
            const float4* s = reinterpret_cast<const float4*>(                     \
                Wg + (size_t)bc * DIMK + (k0) + bsg * 16);                          \
            float4 f0 = s[0], f1 = s[1], f2 = s[2], f3 = s[3];                      \
            BF2 p0 = split2(f0.x, f0.y), p1 = split2(f0.z, f0.w);                   \
            BF2 p2 = split2(f1.x, f1.y), p3 = split2(f1.z, f1.w);                   \
            BF2 p4 = split2(f2.x, f2.y), p5 = split2(f2.z, f2.w);                   \
            BF2 p6 = split2(f3.x, f3.y), p7 = split2(f3.z, f3.w);                   \
            char* bp = (bufp) + OFF_BH + bc * ASTR + bsg * 32;                      \
            *reinterpret_cast<uint4*>(bp)      = make_uint4(p0.h, p1.h, p2.h, p3.h);\
            *reinterpret_cast<uint4*>(bp + 16) = make_uint4(p4.h, p5.h, p6.h, p7.h);\
            char* lp2 = (bufp) + OFF_BL + bc * ASTR + bsg * 32;                     \
            *reinterpret_cast<uint4*>(lp2)      = make_uint4(p0.l, p1.l, p2.l, p3.l);\
            *reinterpret_cast<uint4*>(lp2 + 16) = make_uint4(p4.l, p5.l, p6.l, p7.l);\
        }                                                                          \
    } while (0)

    STAGE(0, smem + SM_BUF);
    __syncthreads();

    #pragma unroll 1
    for (int c = 0; c < NCHUNK; ++c) {
        if (c + 1 < NCHUNK)
            STAGE((c + 1) * KC, smem + SM_BUF + ((c + 1) & 1) * BUFSZ);

        const uint32_t bbase = sb + SM_BUF + (c & 1) * BUFSZ;
        #pragma unroll
        for (int ks = 0; ks < 2; ++ks) {
            uint32_t ah[2][4], al[2][4];
            #pragma unroll
            for (int mi = 0; mi < 2; ++mi) {
                ldm4(ah[mi], bbase + OFF_AH + a_off + mi * (16 * ASTR) + ks * 32);
                ldm4(al[mi], bbase + OFF_AL + a_off + mi * (16 * ASTR) + ks * 32);
            }
            #pragma unroll
            for (int nh = 0; nh < 2; ++nh) {
                uint32_t bh[2][4], bl[2][4];
                #pragma unroll
                for (int ng = 0; ng < 2; ++ng) {
                    uint32_t boff = bbase + b_off + (uint32_t)((nh * 32 + ng * 16) * ASTR)
                                    + ks * 32;
                    ldm4(bh[ng], boff + OFF_BH);
                    ldm4(bl[ng], boff + OFF_BL);
                }
                #pragma unroll
                for (int mi = 0; mi < 2; ++mi) {
                    #pragma unroll
                    for (int nt = 0; nt < 4; ++nt) {
                        const int ng = nt >> 1, rr = (nt & 1) * 2;
                        float* d = acc[mi][nh * 4 + nt];
                        mma_bf16(d, ah[mi], bh[ng][rr], bh[ng][rr + 1]);
                        mma_bf16(d, ah[mi], bl[ng][rr], bl[ng][rr + 1]);
                        mma_bf16(d, al[mi], bh[ng][rr], bh[ng][rr + 1]);
                    }
                }
            }
        }
        __syncthreads();
    }
    #undef STAGE

    // ---- epilogue: bias + per-warp top-2 over warp's 64 cols ----
    const float* sbias = reinterpret_cast<const float*>(smem + SM_BIAS);
    float* sV1 = reinterpret_cast<float*>(smem + SM_V1);
    float* sV2 = reinterpret_cast<float*>(smem + SM_V2);
    int*   sI1 = reinterpret_cast<int*>(smem + SM_I1);

    const int g = lane >> 2, q = lane & 3;
    const int colbase = wn * 64;

    #pragma unroll
    for (int mi = 0; mi < 2; ++mi) {
        #pragma unroll
        for (int h8 = 0; h8 < 2; ++h8) {
            const int row_local = wm * 32 + mi * 16 + h8 * 8 + g;
            float bv = -3.402823466e38f, bv2 = -3.402823466e38f;
            int bc_ = 0;
            #pragma unroll
            for (int nt = 0; nt < 8; ++nt) {
                const int c0 = colbase + nt * 8 + 2 * q;
                float v0 = acc[mi][nt][h8 * 2 + 0] + sbias[c0];
                float v1 = acc[mi][nt][h8 * 2 + 1] + sbias[c0 + 1];
                if (v0 > bv) { bv2 = bv; bv = v0; bc_ = c0; }
                else if (v0 > bv2) bv2 = v0;
                if (v1 > bv) { bv2 = bv; bv = v1; bc_ = c0 + 1; }
                else if (v1 > bv2) bv2 = v1;
            }
            // merge across the 4 lanes sharing this row (q = 0..3)
            #pragma unroll
            for (int off = 1; off <= 2; off <<= 1) {
                float ov  = __shfl_xor_sync(0xffffffffu, bv,  off);
                float ov2 = __shfl_xor_sync(0xffffffffu, bv2, off);
                int   oc  = __shfl_xor_sync(0xffffffffu, bc_, off);
                if (ov > bv || (ov == bv && oc < bc_)) {
                    bv2 = fmaxf(bv, ov2); bv = ov; bc_ = oc;
                } else {
                    bv2 = fmaxf(bv2, ov);
                }
            }
            if (q == 0) {
                sV1[row_local * 4 + wn] = bv;
                sV2[row_local * 4 + wn] = bv2;
                sI1[row_local * 4 + wn] = bc_;
            }
        }
    }
    __syncthreads();

    // ---- final cross-warp merge: one thread per row ----
    if (tid < TM) {
        float bv = sV1[tid * 4], bv2 = sV2[tid * 4];
        int bc_ = sI1[tid * 4];
        #pragma unroll
        for (int w = 1; w < 4; ++w) {
            float ov = sV1[tid * 4 + w], ov2 = sV2[tid * 4 + w];
            int oc = sI1[tid * 4 + w];
            if (ov > bv) { bv2 = fmaxf(bv, ov2); bv = ov; bc_ = oc; }
            else bv2 = fmaxf(bv2, ov);
        }
        const int grow = row0 + tid;
        gidx[grow * NCB + cb] = bc_;
        if (bv - bv2 < GAP_TAU) {
            int pos = atomicAdd(&g_cnt, 1);
            if (pos < RECHECK_CAP) g_list[pos] = grow * NCB + cb;
        }
    }
}

// ---------------------------------------------------------------------------
__global__ void init_kernel() { g_cnt = 0; }

// ---------------------------------------------------------------------------
// Kernel 2: exact fp32 recheck of near-tie (row, cb) pairs (grid-strided).
// CRITICAL: per-column accumulation is a single sequential fma chain over
// k = 0..511 (bitwise identical to the round-1 kernel that matched the
// reference argmax on every pair). Do NOT split into partial sums.
// ---------------------------------------------------------------------------
__global__ __launch_bounds__(256)
void recheck_kernel(const float* __restrict__ x,
                    const float* __restrict__ W,
                    const float* __restrict__ bias,
                    int* __restrict__ gidx)
{
    int n = g_cnt;
    if (n > RECHECK_CAP) n = RECHECK_CAP;

    for (int item = blockIdx.x; item < n; item += gridDim.x) {
        const int enc = g_list[item];
        const int row = enc >> 4;
        const int cb  = enc & 15;
        const int tid = threadIdx.x;
        const int col = tid;

        const float* xr = x + (size_t)row * DIMK;
        const float* wr = W + (size_t)(cb * CS + col) * DIMK;
        float acc = 0.f;
        #pragma unroll 8
        for (int k = 0; k < DIMK; ++k)
            acc = fmaf(xr[k], wr[k], acc);
        float v = acc + bias[cb * CS + col];
        int c = col;

        #pragma unroll
        for (int off = 16; off; off >>= 1) {
            float ov = __shfl_xor_sync(0xffffffffu, v, off);
            int   oc = __shfl_xor_sync(0xffffffffu, c, off);
            if (ov > v || (ov == v && oc < c)) { v = ov; c = oc; }
        }
        __shared__ float rv[8];
        __shared__ int   rc[8];
        if ((tid & 31) == 0) { rv[tid >> 5] = v; rc[tid >> 5] = c; }
        __syncthreads();
        if (tid == 0) {
            #pragma unroll
            for (int w = 1; w < 8; ++w)
                if (rv[w] > v || (rv[w] == v && rc[w] < c)) { v = rv[w]; c = rc[w]; }
            gidx[row * NCB + cb] = c;
        }
        __syncthreads();
    }
}

// ---------------------------------------------------------------------------
// Kernel 3: decode — gather 16 centers per row, sum, scale.
// ---------------------------------------------------------------------------
__global__ __launch_bounds__(128)
void dec_gather_kernel(const float* __restrict__ centers,
                       const int* __restrict__ gidx,
                       const float* __restrict__ centers_scale,
                       float* __restrict__ out)
{
    __shared__ int   sidx[NCB];
    __shared__ float sscale;
    const int row = blockIdx.x;
    const int tid = threadIdx.x;

    if (tid < NCB) sidx[tid] = gidx[row * NCB + tid];
    if (tid == 0)  sscale = expf(10.0f * centers_scale[0]);
    __syncthreads();

    float4 s = make_float4(0.f, 0.f, 0.f, 0.f);
    #pragma unroll
    for (int c = 0; c < NCB; ++c) {
        const float4* p = reinterpret_cast<const float4*>(
            centers + ((size_t)((c << 8) + sidx[c])) * DIMK);
        float4 v = __ldg(&p[tid]);
        s.x += v.x; s.y += v.y; s.z += v.z; s.w += v.w;
    }
    float sc = sscale;
    s.x *= sc; s.y *= sc; s.z *= sc; s.w *= sc;
    reinterpret_cast<float4*>(out)[(size_t)row * (DIMK / 4) + tid] = s;
}

// ---------------------------------------------------------------------------
extern "C" void kernel_launch(void* const* d_in, const int* in_sizes, int n_in,
                              void* d_out, int out_size)
{
    const float* x       = (const float*)d_in[0];
    const float* W       = (const float*)d_in[1];
    const float* b       = (const float*)d_in[2];
    const float* centers = (const float*)d_in[3];
    const float* cscale  = (const float*)d_in[5];
    float* out           = (float*)d_out;

    int* gidx_ptr = nullptr;
    cudaGetSymbolAddress((void**)&gidx_ptr, g_idx);

    cudaFuncSetAttribute(enc_mma_kernel,
                         cudaFuncAttributeMaxDynamicSharedMemorySize, SMEM_TOTAL);

    init_kernel<<<1, 1>>>();
    dim3 grid1(NROWS / TM, NCB);
    enc_mma_kernel<<<grid1, TPB, SMEM_TOTAL>>>(x, W, b, gidx_ptr);
    recheck_kernel<<<RECHECK_BLOCKS, 256>>>(x, W, b, gidx_ptr);
    dec_gather_kernel<<<NROWS, 128>>>(centers, gidx_ptr, cscale, out);
}